// round 8
// baseline (speedup 1.0000x reference)
#include <cuda_runtime.h>
#include <cuda_fp16.h>
#include <cstdint>
#include <cstddef>

#define N_PTS 8192
#define DIMS  128
#define KDIM  144            // 128 data + ext slots (A:[1,1], B:[hi,lo] of -0.5*sq); 9 k-steps
#define KNBR  14
#define CAP   320            // candidate slots per row
#define RSTR  152            // smem row stride in halves (304 B: 16B-aligned, conflict-free ldsm)
#define RSTRB (RSTR * 2)     // 304 bytes
#define TILEB (128 * RSTRB)  // 38912 bytes per 128-row tile

// ---------------- scratch ----------------
__device__ __align__(16) __half g_XA[N_PTS * KDIM];   // rows-as-A: ext = [1,1,0..]
__device__ __align__(16) __half g_XB[N_PTS * KDIM];   // rows-as-B: ext = [hi,lo,0..]
__device__ float  g_SQ[N_PTS];
__device__ float  g_THR[N_PTS];
__device__ int    g_CNT[N_PTS];
__device__ uint2  g_CAND[(size_t)N_PTS * CAP];        // (key bits, col)
__device__ int    g_NBR[N_PTS * KNBR];
__device__ double g_partial_bulk[1024];
__device__ double g_partial_corr[1024];

// ---------------- fast-math ----------------
__device__ __forceinline__ float f_sqrt(float x){ float r; asm("sqrt.approx.f32 %0, %1;" : "=f"(r) : "f"(x)); return r; }
__device__ __forceinline__ float f_rcp (float x){ float r; asm("rcp.approx.f32 %0, %1;"  : "=f"(r) : "f"(x)); return r; }
__device__ __forceinline__ float f_lg2 (float x){ float r; asm("lg2.approx.f32 %0, %1;"  : "=f"(r) : "f"(x)); return r; }
__device__ __forceinline__ float f_ex2 (float x){ float r; asm("ex2.approx.f32 %0, %1;"  : "=f"(r) : "f"(x)); return r; }

#define LN2F   0.69314718055994531f
#define LOG2EF 1.4426950408889634f

__device__ __forceinline__ void cp_async16(uint32_t dst, const void* src) {
    asm volatile("cp.async.cg.shared.global [%0], [%1], 16;" :: "r"(dst), "l"(src));
}
// f16-accumulate HMMA
__device__ __forceinline__ void mma_f16(uint32_t& c0, uint32_t& c1,
                                        uint32_t a0, uint32_t a1, uint32_t a2, uint32_t a3,
                                        uint32_t b0, uint32_t b1) {
    asm volatile("mma.sync.aligned.m16n8k16.row.col.f16.f16.f16.f16 "
                 "{%0,%1}, {%2,%3,%4,%5}, {%6,%7}, {%0,%1};"
                 : "+r"(c0), "+r"(c1) : "r"(a0), "r"(a1), "r"(a2), "r"(a3), "r"(b0), "r"(b1));
}
__device__ __forceinline__ void ldsm4(uint32_t& r0, uint32_t& r1, uint32_t& r2, uint32_t& r3, uint32_t addr) {
    asm volatile("ldmatrix.sync.aligned.m8n8.x4.shared.b16 {%0,%1,%2,%3}, [%4];"
                 : "=r"(r0), "=r"(r1), "=r"(r2), "=r"(r3) : "r"(addr));
}

// ---------------- 1) prep: build g_XA / g_XB + norms + counter reset ----------------
__global__ void prep_kernel(const float* __restrict__ X) {
    int warp = threadIdx.x >> 5, lane = threadIdx.x & 31;
    int row  = blockIdx.x * 8 + warp;
    const float* xr = X + (size_t)row * DIMS;
    float v0 = xr[lane], v1 = xr[lane + 32], v2 = xr[lane + 64], v3 = xr[lane + 96];
    __half* xa = g_XA + (size_t)row * KDIM;
    __half* xb = g_XB + (size_t)row * KDIM;
    __half h0 = __float2half(v0), h1 = __float2half(v1), h2 = __float2half(v2), h3 = __float2half(v3);
    xa[lane] = h0; xa[lane+32] = h1; xa[lane+64] = h2; xa[lane+96] = h3;
    xb[lane] = h0; xb[lane+32] = h1; xb[lane+64] = h2; xb[lane+96] = h3;
    float s = v0*v0 + v1*v1 + v2*v2 + v3*v3;
    #pragma unroll
    for (int off = 16; off; off >>= 1) s += __shfl_xor_sync(0xffffffffu, s, off);
    s = __shfl_sync(0xffffffffu, s, 0);
    if (lane < 16) {
        // A ext: [1, 1, 0...]
        __half ha = (lane < 2) ? __float2half(1.0f) : __float2half(0.0f);
        xa[128 + lane] = ha;
        // B ext: [hi(-0.5 s), residual, 0...]
        float m = -0.5f * s;
        __half hi = __float2half(m);
        __half hb = (lane == 0) ? hi
                  : (lane == 1) ? __float2half(m - __half2float(hi))
                  : __float2half(0.0f);
        xb[128 + lane] = hb;
    }
    if (lane == 0) { g_SQ[row] = s; g_CNT[row] = 0; }
}

// ---- shared fragment-address helpers (warp tile 32x64, 2x4 warp grid) ----
struct FragAddr { uint32_t a_off[2]; uint32_t b_off[4]; };
__device__ __forceinline__ FragAddr frag_addr(int warp, int lane) {
    FragAddr f;
    int wm = warp & 3, wn = warp >> 2;    // NOTE: warp grid 4x2 -> wm rows, wn col-halves
    #pragma unroll
    for (int mt = 0; mt < 2; mt++)
        f.a_off[mt] = (uint32_t)((wm * 32 + mt * 16 + (lane & 15)) * RSTRB + ((lane >> 4) ? 16 : 0));
    #pragma unroll
    for (int bq = 0; bq < 4; bq++)
        f.b_off[bq] = (uint32_t)((wn * 64 + bq * 16 + ((lane >> 3) & 2) * 4 + (lane & 7)) * RSTRB
                                 + ((lane >> 3) & 1) * 16);
    return f;
}
// 9 k-step MMA over a 128x128 tile: acc[2][8][2] (f16x2)
__device__ __forceinline__ void tile_mma(uint32_t sA_u, uint32_t sB_u, const FragAddr& f,
                                         uint32_t acc[2][8][2]) {
    #pragma unroll
    for (int mt = 0; mt < 2; mt++)
        #pragma unroll
        for (int nt = 0; nt < 8; nt++) { acc[mt][nt][0] = 0; acc[mt][nt][1] = 0; }
    #pragma unroll
    for (int kk = 0; kk < 9; kk++) {
        uint32_t kof = (uint32_t)(kk * 32);
        uint32_t afr[2][4];
        #pragma unroll
        for (int mt = 0; mt < 2; mt++)
            ldsm4(afr[mt][0], afr[mt][1], afr[mt][2], afr[mt][3], sA_u + f.a_off[mt] + kof);
        uint32_t bfr[8][2];
        #pragma unroll
        for (int bq = 0; bq < 4; bq++)
            ldsm4(bfr[2*bq][0], bfr[2*bq][1], bfr[2*bq+1][0], bfr[2*bq+1][1],
                  sB_u + f.b_off[bq] + kof);
        #pragma unroll
        for (int mt = 0; mt < 2; mt++)
            #pragma unroll
            for (int nt = 0; nt < 8; nt++)
                mma_f16(acc[mt][nt][0], acc[mt][nt][1],
                        afr[mt][0], afr[mt][1], afr[mt][2], afr[mt][3],
                        bfr[nt][0], bfr[nt][1]);
    }
}

// ======================= Phase 1: threshold from 1/8 subsample =======================
// smem: sA TILEB | sB TILEB | sSc u32[128*66] | stage f32[256*14]
#define P1_SB  TILEB
#define P1_SC  (2 * TILEB)
#define P1_ST  (2 * TILEB + 33792)
#define P1_TOT (P1_ST + 14336)

__global__ __launch_bounds__(256, 1) void thresh_kernel() {
    extern __shared__ __align__(16) char smem[];
    uint32_t sA_u = (uint32_t)__cvta_generic_to_shared(smem);
    uint32_t sB_u = sA_u + P1_SB;
    uint32_t* sSc = (uint32_t*)(smem + P1_SC);
    float*    stK = (float*)(smem + P1_ST);

    int tid = threadIdx.x;
    int rowBlk = blockIdx.x * 128;
    int warp = tid >> 5, lane = tid & 31;
    int wm = warp & 3, wn = warp >> 2;
    int grp = lane >> 2, tig = lane & 3;
    FragAddr fa = frag_addr(warp, lane);

    // A tile: 2304 16B chunks
    #pragma unroll
    for (int i = 0; i < 9; i++) {
        int c = tid + i * 256;
        int r = c / 18, q = c % 18;
        cp_async16(sA_u + (uint32_t)(r * RSTRB + q * 16),
                   g_XA + (size_t)(rowBlk + r) * KDIM + q * 8);
    }
    asm volatile("cp.async.commit_group;");

    float bk[KNBR];
    #pragma unroll
    for (int s = 0; s < KNBR; s++) bk[s] = -3.4e38f;
    int srow = tid >> 1, seg = tid & 1;

    for (int t = 0; t < 8; t++) {
        #pragma unroll
        for (int i = 0; i < 9; i++) {
            int c = tid + i * 256;
            int r = c / 18, q = c % 18;
            cp_async16(sB_u + (uint32_t)(r * RSTRB + q * 16),
                       g_XB + (size_t)(8 * (t * 128 + r)) * KDIM + q * 8);
        }
        asm volatile("cp.async.commit_group;");
        asm volatile("cp.async.wait_group 0;");
        __syncthreads();

        uint32_t acc[2][8][2];
        tile_mma(sA_u, sB_u, fa, acc);

        #pragma unroll
        for (int mt = 0; mt < 2; mt++)
            #pragma unroll
            for (int nt = 0; nt < 8; nt++) {
                int lr = wm * 32 + mt * 16 + grp;
                int cp = wn * 32 + nt * 4 + tig;
                sSc[lr * 66 + cp]       = acc[mt][nt][0];
                sSc[(lr + 8) * 66 + cp] = acc[mt][nt][1];
            }
        __syncthreads();
        const uint32_t* prow = sSc + srow * 66 + seg * 32;
        #pragma unroll 8
        for (int c = 0; c < 32; c++) {
            __half2 h = *(const __half2*)&prow[c];
            float v0 = __low2float(h), v1 = __high2float(h);
            if (v0 > bk[KNBR - 1]) { float cv = v0;
                #pragma unroll
                for (int s = 0; s < KNBR; s++) if (cv > bk[s]) { float tf = bk[s]; bk[s] = cv; cv = tf; } }
            if (v1 > bk[KNBR - 1]) { float cv = v1;
                #pragma unroll
                for (int s = 0; s < KNBR; s++) if (cv > bk[s]) { float tf = bk[s]; bk[s] = cv; cv = tf; } }
        }
        __syncthreads();
    }
    #pragma unroll
    for (int s = 0; s < KNBR; s++) stK[tid * KNBR + s] = bk[s];
    __syncthreads();
    if (tid < 128) {
        const float* k0 = stK + (tid * 2) * KNBR;
        const float* k1 = stK + (tid * 2 + 1) * KNBR;
        int p0 = 0, p1 = 0; float v = -3.4e38f;
        #pragma unroll
        for (int s = 0; s < KNBR; s++) {
            if (k0[p0] >= k1[p1]) v = k0[p0++]; else v = k1[p1++];
        }
        g_THR[rowBlk + tid] = v;
    }
}

// ======================= Phase 2: full GEMM + threshold filter =======================
#define P2_TOT (3 * TILEB)    // A + 2 B buffers = 116736

__global__ __launch_bounds__(256, 1) void filter_kernel() {
    extern __shared__ __align__(16) char smem[];
    uint32_t sA_u = (uint32_t)__cvta_generic_to_shared(smem);
    uint32_t sB_u = sA_u + TILEB;

    int tid = threadIdx.x;
    int warp = tid >> 5, lane = tid & 31;
    int wm = warp & 3, wn = warp >> 2;
    int grp = lane >> 2, tig = lane & 3;
    int rb = blockIdx.x >> 2, quarter = blockIdx.x & 3;
    int rowBlk = rb * 128, colBase = quarter * 2048;
    FragAddr fa = frag_addr(warp, lane);

    int crow[9], cqof[9];
    #pragma unroll
    for (int i = 0; i < 9; i++) { int c = tid + i * 256; crow[i] = c / 18; cqof[i] = c % 18; }

    #pragma unroll
    for (int i = 0; i < 9; i++)
        cp_async16(sA_u + (uint32_t)(crow[i] * RSTRB + cqof[i] * 16),
                   g_XA + (size_t)(rowBlk + crow[i]) * KDIM + cqof[i] * 8);
    #pragma unroll
    for (int i = 0; i < 9; i++)
        cp_async16(sB_u + (uint32_t)(crow[i] * RSTRB + cqof[i] * 16),
                   g_XB + (size_t)(colBase + crow[i]) * KDIM + cqof[i] * 8);
    asm volatile("cp.async.commit_group;");
    #pragma unroll
    for (int i = 0; i < 9; i++)
        cp_async16(sB_u + (uint32_t)TILEB + (uint32_t)(crow[i] * RSTRB + cqof[i] * 16),
                   g_XB + (size_t)(colBase + 128 + crow[i]) * KDIM + cqof[i] * 8);
    asm volatile("cp.async.commit_group;");

    float T[2][2]; int rowg[2][2];
    #pragma unroll
    for (int mt = 0; mt < 2; mt++)
        #pragma unroll
        for (int rh = 0; rh < 2; rh++) {
            rowg[mt][rh] = rowBlk + wm * 32 + mt * 16 + grp + rh * 8;
            T[mt][rh] = g_THR[rowg[mt][rh]];
        }

    asm volatile("cp.async.wait_group 1;");       // A + B0 done (this thread's chunks)

    for (int t = 0; t < 16; t++) {
        __syncthreads();                           // B(t) visible block-wide
        uint32_t bbuf = sB_u + (uint32_t)(t & 1) * (uint32_t)TILEB;

        uint32_t acc[2][8][2];
        tile_mma(sA_u, bbuf, fa, acc);

        // ---- register filter ----
        int colT = colBase + t * 128 + wn * 64 + tig * 2;
        #pragma unroll
        for (int mt = 0; mt < 2; mt++) {
            #pragma unroll
            for (int rh = 0; rh < 2; rh++) {
                __half2 gm = *(__half2*)&acc[mt][0][rh];
                #pragma unroll
                for (int nt = 1; nt < 8; nt++) gm = __hmax2(gm, *(__half2*)&acc[mt][nt][rh]);
                float gmf = fmaxf(__low2float(gm), __high2float(gm));
                float Tf = T[mt][rh];
                if (gmf >= Tf) {
                    int row = rowg[mt][rh];
                    #pragma unroll
                    for (int nt = 0; nt < 8; nt++) {
                        __half2 hv = *(__half2*)&acc[mt][nt][rh];
                        float v0 = __low2float(hv), v1 = __high2float(hv);
                        if (v0 >= Tf) {
                            int pos = atomicAdd(&g_CNT[row], 1);
                            if (pos < CAP) g_CAND[(size_t)row * CAP + pos] =
                                make_uint2(__float_as_uint(v0), (uint32_t)(colT + nt * 8));
                        }
                        if (v1 >= Tf) {
                            int pos = atomicAdd(&g_CNT[row], 1);
                            if (pos < CAP) g_CAND[(size_t)row * CAP + pos] =
                                make_uint2(__float_as_uint(v1), (uint32_t)(colT + nt * 8 + 1));
                        }
                    }
                }
            }
        }
        __syncthreads();                           // all reads of buf (t&1) done
        if (t + 2 < 16) {
            uint32_t bdst = sB_u + (uint32_t)(t & 1) * (uint32_t)TILEB;
            const __half* bsrc = g_XB + (size_t)(colBase + (t + 2) * 128) * KDIM;
            #pragma unroll
            for (int i = 0; i < 9; i++)
                cp_async16(bdst + (uint32_t)(crow[i] * RSTRB + cqof[i] * 16),
                           bsrc + (size_t)crow[i] * KDIM + cqof[i] * 8);
            asm volatile("cp.async.commit_group;");
            asm volatile("cp.async.wait_group 1;");
        } else if (t + 1 < 16) {
            asm volatile("cp.async.wait_group 0;");
        }
    }
}

// ======================= Phase 3: select top-14 from candidates =======================
__global__ void select_topk() {
    int warp = threadIdx.x >> 5, lane = threadIdx.x & 31;
    int row  = blockIdx.x * 8 + warp;
    int cnt = g_CNT[row]; if (cnt > CAP) cnt = CAP;

    float bk[KNBR]; int bi[KNBR];
    #pragma unroll
    for (int s = 0; s < KNBR; s++) { bk[s] = -3.4e38f; bi[s] = 0x7fffffff; }
    for (int c = lane; c < cnt; c += 32) {
        uint2 e = g_CAND[(size_t)row * CAP + c];
        float cv = __uint_as_float(e.x); int ci = (int)e.y;
        if (cv > bk[KNBR - 1] || (cv == bk[KNBR - 1] && ci < bi[KNBR - 1])) {
            #pragma unroll
            for (int s = 0; s < KNBR; s++)
                if (cv > bk[s] || (cv == bk[s] && ci < bi[s])) {
                    float tf = bk[s]; bk[s] = cv; cv = tf;
                    int   ti = bi[s]; bi[s] = ci; ci = ti;
                }
        }
    }
    int p = 0;
    for (int r = 0; r < KNBR; r++) {
        float cand = (p < KNBR) ? bk[p] : -3.4e38f;
        int   cidx = (p < KNBR) ? bi[p] : 0x7fffffff;
        int   owner = lane;
        #pragma unroll
        for (int off = 16; off; off >>= 1) {
            float ov = __shfl_xor_sync(0xffffffffu, cand, off);
            int   oi = __shfl_xor_sync(0xffffffffu, cidx, off);
            int   ow = __shfl_xor_sync(0xffffffffu, owner, off);
            if (ov > cand || (ov == cand && oi < cidx)) { cand = ov; cidx = oi; owner = ow; }
        }
        if (lane == owner) p++;
        if (lane == 0) g_NBR[row * KNBR + r] = cidx;
    }
}

// ---------------- bulk lo-dim loss (triangular x2) ----------------
__global__ void bulk_kernel(const float* __restrict__ LO) {
    int ibase = blockIdx.x * 256, jbase = blockIdx.y * 256;
    if (jbase + 256 <= ibase) return;
    __shared__ float2 sLo[256];
    __shared__ double sred[256];
    int tid = threadIdx.x;
    const float2* lo2 = (const float2*)LO;
    int i = ibase + tid;
    float2 me = lo2[i];
    sLo[tid] = lo2[jbase + tid];
    __syncthreads();

    float accf = 0.f;
    if (jbase >= ibase + 256) {
        #pragma unroll 4
        for (int j = 0; j < 256; j++) {
            float2 o = sLo[j];
            float dx = me.x - o.x, dy = me.y - o.y;
            float d  = f_sqrt(fmaf(dx, dx, dy * dy));
            float r  = f_rcp(1.0f + d);
            accf += f_lg2((1.0f - r) + 1e-10f);
        }
        accf *= 2.0f;
    } else {
        #pragma unroll 4
        for (int j = 0; j < 256; j++) {
            int jg = jbase + j;
            float2 o = sLo[j];
            float dx = me.x - o.x, dy = me.y - o.y;
            float d  = f_sqrt(fmaf(dx, dx, dy * dy));
            float r  = f_rcp(1.0f + d);
            float term = f_lg2((1.0f - r) + 1e-10f);
            float w = (jg > i) ? 2.0f : ((jg == i) ? 1.0f : 0.0f);
            accf += w * term;
        }
    }
    sred[tid] = (double)(accf * LN2F);
    __syncthreads();
    for (int off = 128; off; off >>= 1) { if (tid < off) sred[tid] += sred[tid + off]; __syncthreads(); }
    if (tid == 0) g_partial_bulk[blockIdx.y * 32 + blockIdx.x] = sred[0];
}

// ---------------- exact neighbor correction ----------------
__global__ void corr_kernel(const float* __restrict__ X, const float* __restrict__ LO) {
    __shared__ double wsum[8];
    int warp = threadIdx.x >> 5, lane = threadIdx.x & 31;
    int row  = blockIdx.x * 8 + warp;
    const float* xi = X + (size_t)row * DIMS;
    float a0 = xi[lane], a1 = xi[lane + 32], a2 = xi[lane + 64], a3 = xi[lane + 96];
    const float2* lo2 = (const float2*)LO;
    float2 li = lo2[row];
    float sqi = g_SQ[row];

    float acc = 0.f;
    for (int n = 0; n < KNBR; n++) {
        int j = g_NBR[row * KNBR + n];
        const float* xj = X + (size_t)j * DIMS;
        float dot = a0 * xj[lane] + a1 * xj[lane + 32] + a2 * xj[lane + 64] + a3 * xj[lane + 96];
        #pragma unroll
        for (int off = 16; off; off >>= 1) dot += __shfl_xor_sync(0xffffffffu, dot, off);
        float d2h = fmaxf(sqi + g_SQ[j] - 2.f * dot, 0.f);
        float hd = f_sqrt(d2h);
        float hs = f_ex2(-LOG2EF * hd);
        float2 lj = lo2[j];
        float dx = li.x - lj.x, dy = li.y - lj.y;
        float ld = f_sqrt(fmaf(dx, dx, dy * dy));
        float r  = f_rcp(1.0f + ld);
        float A  = hs * (f_lg2(r + 1e-10f) * LN2F);
        float Bs = f_lg2((1.0f - r) + 1e-10f) * LN2F;
        acc += (A - Bs);
    }
    if (lane == 0) wsum[warp] = (double)acc;
    __syncthreads();
    if (threadIdx.x == 0) {
        double s = 0;
        for (int k = 0; k < 8; k++) s += wsum[k];
        g_partial_corr[blockIdx.x] = s;
    }
}

// ---------------- deterministic final reduce ----------------
__global__ void final_kernel(float* __restrict__ out) {
    __shared__ double sred[256];
    int t = threadIdx.x;
    double s = 0;
    for (int k = t; k < 1024; k += 256) s += g_partial_bulk[k];
    for (int k = t; k < 1024; k += 256) s += g_partial_corr[k];
    sred[t] = s;
    __syncthreads();
    for (int off = 128; off; off >>= 1) { if (t < off) sred[t] += sred[t + off]; __syncthreads(); }
    if (t == 0) out[0] = (float)(-(sred[0] / 67108864.0) * 100.0);
}

// ---------------- launch ----------------
extern "C" void kernel_launch(void* const* d_in, const int* in_sizes, int n_in,
                              void* d_out, int out_size) {
    const float* X; const float* LO;
    if (in_sizes[0] == N_PTS * DIMS) { X = (const float*)d_in[0]; LO = (const float*)d_in[1]; }
    else                             { X = (const float*)d_in[1]; LO = (const float*)d_in[0]; }

    cudaFuncSetAttribute(thresh_kernel, cudaFuncAttributeMaxDynamicSharedMemorySize, P1_TOT);
    cudaFuncSetAttribute(filter_kernel, cudaFuncAttributeMaxDynamicSharedMemorySize, P2_TOT);

    prep_kernel  <<<N_PTS / 8, 256>>>(X);
    thresh_kernel<<<64, 256, P1_TOT>>>();
    filter_kernel<<<256, 256, P2_TOT>>>();
    select_topk  <<<N_PTS / 8, 256>>>();
    bulk_kernel  <<<dim3(32, 32), 256>>>(LO);
    corr_kernel  <<<N_PTS / 8, 256>>>(X, LO);
    final_kernel <<<1, 256>>>((float*)d_out);
}